// round 1
// baseline (speedup 1.0000x reference)
#include <cuda_runtime.h>
#include <math.h>

// Problem constants
#define BATCH 4
#define CCH   512     // C
#define ICH   256     // inter_plane
#define NPIX  4096    // H*W
#define BNEPS 1e-5f

// ---------------------------------------------------------------------------
// Scratch (device globals — no allocations allowed)
// ---------------------------------------------------------------------------
static __device__ float g_k [(size_t)BATCH * ICH * NPIX];   // 16.8 MB
static __device__ float g_v [(size_t)BATCH * ICH * NPIX];
static __device__ float g_q [(size_t)BATCH * ICH * NPIX];
static __device__ float g_S [(size_t)BATCH * NPIX * NPIX];  // 268 MB (attn)
static __device__ float g_av [(size_t)BATCH * ICH * NPIX];
static __device__ float g_avw[(size_t)BATCH * ICH * NPIX];
static __device__ float g_sc1[ICH], g_sh1[ICH];
static __device__ float g_sc2[CCH], g_sh2[CCH];

// ---------------------------------------------------------------------------
// Fold BN constants:
//   bn1: y = (x - m1)*g1/sqrt(v1+eps) + b1      -> x*sc1 + sh1
//   bn2 applied to (Wx + bout):
//        y = (Wx + bout - m2)*g2/sqrt(v2+eps) + b2 -> (Wx)*sc2 + sh2
// ---------------------------------------------------------------------------
__global__ void fold_kernel(const float* __restrict__ g1, const float* __restrict__ b1,
                            const float* __restrict__ m1, const float* __restrict__ v1,
                            const float* __restrict__ g2, const float* __restrict__ b2,
                            const float* __restrict__ m2, const float* __restrict__ v2,
                            const float* __restrict__ bout)
{
    int i = blockIdx.x * blockDim.x + threadIdx.x;
    if (i < ICH) {
        float s = g1[i] * rsqrtf(v1[i] + BNEPS);
        g_sc1[i] = s;
        g_sh1[i] = b1[i] - m1[i] * s;
    }
    if (i < CCH) {
        float s = g2[i] * rsqrtf(v2[i] + BNEPS);
        g_sc2[i] = s;
        g_sh2[i] = (bout[i] - m2[i]) * s + b2[i];
    }
}

// ---------------------------------------------------------------------------
// Generic batched fp32 GEMM: C[m,n] = sum_k A[m,k] * B[k,n]  (+ epilogue)
//   TRANSA = false : A stored row-major [M,K] (lda = K)
//   TRANSA = true  : A stored row-major [K,M] (lda = M) -> A[m,k] = Astore[k,m]
//   B always row-major [K,N].
//   EPI = 0 : C = acc + (bias ? bias[m] : 0)
//   EPI = 1 : C = acc*scale[m] + shift[m]
//   EPI = 2 : C = relu(acc*scale[m] + shift[m] + resid[m,n])
// Requirements (all satisfied here): M%128==0, N%128==0, K%8==0.
// Tile: 128x128x8, 256 threads, 8x8 micro-tile per thread.
// ---------------------------------------------------------------------------
template<bool TRANSA, int EPI>
__global__ __launch_bounds__(256)
void gemm128(const float* __restrict__ A, const float* __restrict__ Bm,
             float* __restrict__ Cm,
             int M, int N, int K,
             size_t sA, size_t sB, size_t sC,
             const float* __restrict__ bias,
             const float* __restrict__ scale, const float* __restrict__ shift,
             const float* __restrict__ resid, size_t sR)
{
    __shared__ float As[8][132];   // +4 pad: kills transpose-write conflicts
    __shared__ float Bs[8][128];

    const int bz = blockIdx.z;
    const float* Ab = A  + (size_t)bz * sA;
    const float* Bb = Bm + (size_t)bz * sB;
    float*       Cb = Cm + (size_t)bz * sC;

    const int bm = blockIdx.y * 128;
    const int bn = blockIdx.x * 128;
    const int t  = threadIdx.x;
    const int tx = t & 15;         // 0..15  -> 8-col group
    const int ty = t >> 4;         // 0..15  -> 8-row group

    float acc[8][8];
#pragma unroll
    for (int i = 0; i < 8; i++)
#pragma unroll
        for (int j = 0; j < 8; j++) acc[i][j] = 0.0f;

    for (int k0 = 0; k0 < K; k0 += 8) {
        // ---- load B tile: 8 x 128, coalesced along n
#pragma unroll
        for (int i = 0; i < 4; i++) {
            int idx = t + i * 256;
            int kk = idx >> 7, n = idx & 127;
            Bs[kk][n] = Bb[(size_t)(k0 + kk) * N + bn + n];
        }
        // ---- load A tile into As[k][m]
        if (TRANSA) {
#pragma unroll
            for (int i = 0; i < 4; i++) {
                int idx = t + i * 256;
                int kk = idx >> 7, m = idx & 127;
                As[kk][m] = Ab[(size_t)(k0 + kk) * M + bm + m];
            }
        } else {
            int m  = t >> 1;
            int kb = (t & 1) * 4;
            float4 a4 = *(const float4*)&Ab[(size_t)(bm + m) * K + k0 + kb];
            As[kb + 0][m] = a4.x;
            As[kb + 1][m] = a4.y;
            As[kb + 2][m] = a4.z;
            As[kb + 3][m] = a4.w;
        }
        __syncthreads();

#pragma unroll
        for (int kk = 0; kk < 8; kk++) {
            float af[8], bf[8];
            *(float4*)&af[0] = *(const float4*)&As[kk][ty * 8];
            *(float4*)&af[4] = *(const float4*)&As[kk][ty * 8 + 4];
            *(float4*)&bf[0] = *(const float4*)&Bs[kk][tx * 8];
            *(float4*)&bf[4] = *(const float4*)&Bs[kk][tx * 8 + 4];
#pragma unroll
            for (int i = 0; i < 8; i++)
#pragma unroll
                for (int j = 0; j < 8; j++)
                    acc[i][j] = fmaf(af[i], bf[j], acc[i][j]);
        }
        __syncthreads();
    }

    // ---- epilogue
#pragma unroll
    for (int i = 0; i < 8; i++) {
        int m = bm + ty * 8 + i;
        float sc = 1.0f, sh = 0.0f;
        if (EPI == 0) {
            sh = bias ? bias[m] : 0.0f;
        } else {
            sc = scale[m];
            sh = shift[m];
        }
        float* crow = &Cb[(size_t)m * N + bn + tx * 8];
        float out[8];
#pragma unroll
        for (int j = 0; j < 8; j++) out[j] = acc[i][j] * sc + sh;
        if (EPI == 2) {
            const float* rrow = &resid[(size_t)bz * sR + (size_t)m * N + bn + tx * 8];
            float4 r0 = *(const float4*)&rrow[0];
            float4 r1 = *(const float4*)&rrow[4];
            out[0] += r0.x; out[1] += r0.y; out[2] += r0.z; out[3] += r0.w;
            out[4] += r1.x; out[5] += r1.y; out[6] += r1.z; out[7] += r1.w;
#pragma unroll
            for (int j = 0; j < 8; j++) out[j] = out[j] > 0.0f ? out[j] : 0.0f;
        }
        *(float4*)&crow[0] = make_float4(out[0], out[1], out[2], out[3]);
        *(float4*)&crow[4] = make_float4(out[4], out[5], out[6], out[7]);
    }
}

// ---------------------------------------------------------------------------
// Row softmax over axis m of S[b][n][m] (row length 4096), in-place.
// One block (256 threads) per row; 16 floats per thread in registers.
// ---------------------------------------------------------------------------
__global__ __launch_bounds__(256)
void softmax_rows(float* __restrict__ S)
{
    __shared__ float red[256];
    size_t row = blockIdx.x;                    // 0 .. BATCH*NPIX-1
    float* r = S + row * NPIX;
    int t = threadIdx.x;

    float4 v[4];
#pragma unroll
    for (int i = 0; i < 4; i++) v[i] = ((const float4*)r)[t + i * 256];

    // --- max reduce
    float mx = v[0].x;
#pragma unroll
    for (int i = 0; i < 4; i++) {
        mx = fmaxf(mx, fmaxf(fmaxf(v[i].x, v[i].y), fmaxf(v[i].z, v[i].w)));
    }
    red[t] = mx;
    __syncthreads();
#pragma unroll
    for (int s = 128; s > 0; s >>= 1) {
        if (t < s) red[t] = fmaxf(red[t], red[t + s]);
        __syncthreads();
    }
    mx = red[0];
    __syncthreads();

    // --- exp + sum
    float sum = 0.0f;
#pragma unroll
    for (int i = 0; i < 4; i++) {
        v[i].x = __expf(v[i].x - mx); sum += v[i].x;
        v[i].y = __expf(v[i].y - mx); sum += v[i].y;
        v[i].z = __expf(v[i].z - mx); sum += v[i].z;
        v[i].w = __expf(v[i].w - mx); sum += v[i].w;
    }
    red[t] = sum;
    __syncthreads();
#pragma unroll
    for (int s = 128; s > 0; s >>= 1) {
        if (t < s) red[t] += red[t + s];
        __syncthreads();
    }
    float inv = 1.0f / red[0];

    // --- normalize + write back
#pragma unroll
    for (int i = 0; i < 4; i++) {
        v[i].x *= inv; v[i].y *= inv; v[i].z *= inv; v[i].w *= inv;
        ((float4*)r)[t + i * 256] = v[i];
    }
}

// ---------------------------------------------------------------------------
// Launch
// ---------------------------------------------------------------------------
extern "C" void kernel_launch(void* const* d_in, const int* in_sizes, int n_in,
                              void* d_out, int out_size)
{
    const float* xA   = (const float*)d_in[0];
    const float* wk   = (const float*)d_in[1];
    const float* bk   = (const float*)d_in[2];
    const float* wv   = (const float*)d_in[3];
    const float* bv   = (const float*)d_in[4];
    const float* wq   = (const float*)d_in[5];
    const float* bq   = (const float*)d_in[6];
    const float* wwg  = (const float*)d_in[7];
    const float* bn1g = (const float*)d_in[8];
    const float* bn1b = (const float*)d_in[9];
    const float* bn1m = (const float*)d_in[10];
    const float* bn1v = (const float*)d_in[11];
    const float* wout = (const float*)d_in[12];
    const float* bout = (const float*)d_in[13];
    const float* bn2g = (const float*)d_in[14];
    const float* bn2b = (const float*)d_in[15];
    const float* bn2m = (const float*)d_in[16];
    const float* bn2v = (const float*)d_in[17];
    float* out = (float*)d_out;

    float *pk, *pv, *pq, *pS, *pav, *pavw;
    cudaGetSymbolAddress((void**)&pk,   g_k);
    cudaGetSymbolAddress((void**)&pv,   g_v);
    cudaGetSymbolAddress((void**)&pq,   g_q);
    cudaGetSymbolAddress((void**)&pS,   g_S);
    cudaGetSymbolAddress((void**)&pav,  g_av);
    cudaGetSymbolAddress((void**)&pavw, g_avw);
    float *psc1, *psh1, *psc2, *psh2;
    cudaGetSymbolAddress((void**)&psc1, g_sc1);
    cudaGetSymbolAddress((void**)&psh1, g_sh1);
    cudaGetSymbolAddress((void**)&psc2, g_sc2);
    cudaGetSymbolAddress((void**)&psh2, g_sh2);

    // 0) fold BN constants
    fold_kernel<<<1, 512>>>(bn1g, bn1b, bn1m, bn1v, bn2g, bn2b, bn2m, bn2v, bout);

    const size_t sX  = (size_t)CCH * NPIX;   // xA batch stride
    const size_t sIC = (size_t)ICH * NPIX;   // k/v/q/av/avw batch stride
    const size_t sS  = (size_t)NPIX * NPIX;  // S batch stride

    dim3 blk(256);

    // 1) projections: k/v/q[b][o][n] = W[o][c] * xA[b][c][n] + bias[o]
    {
        dim3 grd(NPIX / 128, ICH / 128, BATCH);
        gemm128<false, 0><<<grd, blk>>>(wk, xA, pk, ICH, NPIX, CCH,
                                        0, sX, sIC, bk, nullptr, nullptr, nullptr, 0);
        gemm128<false, 0><<<grd, blk>>>(wv, xA, pv, ICH, NPIX, CCH,
                                        0, sX, sIC, bv, nullptr, nullptr, nullptr, 0);
        gemm128<false, 0><<<grd, blk>>>(wq, xA, pq, ICH, NPIX, CCH,
                                        0, sX, sIC, bq, nullptr, nullptr, nullptr, 0);
    }

    // 2) S[b][n][m] = sum_c v[b][c][n] * q[b][c][m]   (A = v^T, TRANSA)
    {
        dim3 grd(NPIX / 128, NPIX / 128, BATCH);
        gemm128<true, 0><<<grd, blk>>>(pv, pq, pS, NPIX, NPIX, ICH,
                                       sIC, sIC, sS, nullptr, nullptr, nullptr, nullptr, 0);
    }

    // 3) softmax over m, in place
    softmax_rows<<<BATCH * NPIX, 256>>>(pS);

    // 4) av[b][c][m] = sum_n k[b][c][n] * attn[b][n][m]
    {
        dim3 grd(NPIX / 128, ICH / 128, BATCH);
        gemm128<false, 0><<<grd, blk>>>(pk, pS, pav, ICH, NPIX, NPIX,
                                        sIC, sS, sIC, nullptr, nullptr, nullptr, nullptr, 0);
    }

    // 5) avw = bn1(wwg @ av)
    {
        dim3 grd(NPIX / 128, ICH / 128, BATCH);
        gemm128<false, 1><<<grd, blk>>>(wwg, pav, pavw, ICH, NPIX, ICH,
                                        0, sIC, sIC, nullptr, psc1, psh1, nullptr, 0);
    }

    // 6) out = relu(bn2(wout @ avw + bout) + xA)
    {
        dim3 grd(NPIX / 128, CCH / 128, BATCH);
        gemm128<false, 2><<<grd, blk>>>(wout, pavw, out, CCH, NPIX, ICH,
                                        0, sIC, sX, nullptr, psc2, psh2, xA, sX);
    }
}

// round 3
// speedup vs baseline: 5.6082x; 5.6082x over previous
#include <cuda_runtime.h>
#include <cuda_bf16.h>
#include <cstdint>

#define BATCH 4
#define CCH   512
#define ICH   256
#define NPIX  4096
#define BNEPS 1e-5f

// ---------------------------------------------------------------------------
// Scratch (device globals)
// ---------------------------------------------------------------------------
static __device__ uint16_t g_kb  [(size_t)BATCH * ICH * NPIX];   // k  [IC,N] bf16
static __device__ uint16_t g_vT  [(size_t)BATCH * NPIX * ICH];   // v^T [N,IC] bf16
static __device__ uint16_t g_qb  [(size_t)BATCH * ICH * NPIX];   // q  [IC,N] bf16
static __device__ float    g_S   [(size_t)BATCH * NPIX * NPIX];  // logits fp32
static __device__ uint16_t g_attn[(size_t)BATCH * NPIX * NPIX];  // softmax bf16
static __device__ uint16_t g_avb [(size_t)BATCH * ICH * NPIX];
static __device__ uint16_t g_avwb[(size_t)BATCH * ICH * NPIX];
static __device__ float g_sc1[ICH], g_sh1[ICH], g_sc2[CCH], g_sh2[CCH];

// ---------------------------------------------------------------------------
// Helpers
// ---------------------------------------------------------------------------
__device__ __forceinline__ uint32_t cvt2(float a, float b) {
    __nv_bfloat162 h = __floats2bfloat162_rn(a, b);
    return *(uint32_t*)&h;
}
__device__ __forceinline__ uint16_t f2b(float x) {
    __nv_bfloat16 b = __float2bfloat16_rn(x);
    return *(uint16_t*)&b;
}
__device__ __forceinline__ void ldsm4(uint32_t* r, uint32_t addr) {
    asm volatile("ldmatrix.sync.aligned.m8n8.x4.shared.b16 {%0,%1,%2,%3}, [%4];"
                 : "=r"(r[0]), "=r"(r[1]), "=r"(r[2]), "=r"(r[3]) : "r"(addr));
}
__device__ __forceinline__ void ldsm4t(uint32_t* r, uint32_t addr) {
    asm volatile("ldmatrix.sync.aligned.m8n8.x4.trans.shared.b16 {%0,%1,%2,%3}, [%4];"
                 : "=r"(r[0]), "=r"(r[1]), "=r"(r[2]), "=r"(r[3]) : "r"(addr));
}
__device__ __forceinline__ void mma16816(float* c, const uint32_t* a,
                                         uint32_t b0, uint32_t b1) {
    asm volatile(
        "mma.sync.aligned.m16n8k16.row.col.f32.bf16.bf16.f32 "
        "{%0,%1,%2,%3}, {%4,%5,%6,%7}, {%8,%9}, {%0,%1,%2,%3};"
        : "+f"(c[0]), "+f"(c[1]), "+f"(c[2]), "+f"(c[3])
        : "r"(a[0]), "r"(a[1]), "r"(a[2]), "r"(a[3]), "r"(b0), "r"(b1));
}

// ---------------------------------------------------------------------------
// Fold BN constants
// ---------------------------------------------------------------------------
__global__ void fold_kernel(const float* __restrict__ g1, const float* __restrict__ b1,
                            const float* __restrict__ m1, const float* __restrict__ v1,
                            const float* __restrict__ g2, const float* __restrict__ b2,
                            const float* __restrict__ m2, const float* __restrict__ v2,
                            const float* __restrict__ bout)
{
    int i = blockIdx.x * blockDim.x + threadIdx.x;
    if (i < ICH) {
        float s = g1[i] * rsqrtf(v1[i] + BNEPS);
        g_sc1[i] = s;
        g_sh1[i] = b1[i] - m1[i] * s;
    }
    if (i < CCH) {
        float s = g2[i] * rsqrtf(v2[i] + BNEPS);
        g_sc2[i] = s;
        g_sh2[i] = (bout[i] - m2[i]) * s + b2[i];
    }
}

// ---------------------------------------------------------------------------
// HMMA GEMM: D[m,n] = sum_k A[m,k] * B[k,n] (+ epilogue)
//   A: [M,K] row-major (float or bf16), B: [K,N] row-major (float or bf16).
//   Tile 128x128x32, 256 thr = 8 warps (4m x 2n), warp = 32m x 64n,
//   mma.sync m16n8k16 bf16->fp32, double-buffered smem.
// EPI: 0 +bias[m] -> bf16 [M,N]
//      1 +bias[m] -> bf16 TRANSPOSED [N,M]
//      2 none     -> fp32 [M,N]
//      3 *scale[m]+shift[m] -> bf16 [M,N]
//      4 *scale[m]+shift[m]+resid, relu -> fp32 [M,N]
// ---------------------------------------------------------------------------
template<typename TA, typename TB, int EPI>
__global__ __launch_bounds__(256)
void hmma_gemm(const TA* __restrict__ A, const TB* __restrict__ B, void* __restrict__ Cv,
               int M, int N, int K, size_t strA, size_t strB, size_t strC,
               const float* __restrict__ bias,
               const float* __restrict__ scale, const float* __restrict__ shift,
               const float* __restrict__ resid, size_t sR)
{
    constexpr int LDA = 40;    // padded stride (elems) -> conflict-free ldmatrix
    constexpr int LDB = 136;
    __shared__ uint16_t smA[2][128 * LDA];
    __shared__ uint16_t smB[2][32 * LDB];

    const int tid  = threadIdx.x;
    const int lane = tid & 31, wid = tid >> 5;
    const int wm = wid & 3, wn = wid >> 2;
    const int bz = blockIdx.z;
    const int bm = blockIdx.y * 128, bn = blockIdx.x * 128;
    const TA* Ag = A + (size_t)bz * strA;
    const TB* Bg = B + (size_t)bz * strB;

    float acc[2][8][4];
#pragma unroll
    for (int i = 0; i < 2; i++)
#pragma unroll
        for (int j = 0; j < 8; j++)
#pragma unroll
            for (int l = 0; l < 4; l++) acc[i][j][l] = 0.f;

    uint32_t la[8], lb[8];

    auto loadA = [&](int kc) {
        if constexpr (sizeof(TA) == 4) {
#pragma unroll
            for (int p = 0; p < 4; p++) {
                int row = (tid >> 3) + p * 32, f4 = tid & 7;
                float4 v = *(const float4*)(Ag + (size_t)(bm + row) * K + kc + f4 * 4);
                la[2 * p] = cvt2(v.x, v.y);
                la[2 * p + 1] = cvt2(v.z, v.w);
            }
        } else {
#pragma unroll
            for (int p = 0; p < 2; p++) {
                int row = (tid >> 2) + p * 64, u4 = tid & 3;
                uint4 v = *(const uint4*)(Ag + (size_t)(bm + row) * K + kc + u4 * 8);
                la[4 * p] = v.x; la[4 * p + 1] = v.y;
                la[4 * p + 2] = v.z; la[4 * p + 3] = v.w;
            }
        }
    };
    auto storeA = [&](int buf) {
        if constexpr (sizeof(TA) == 4) {
#pragma unroll
            for (int p = 0; p < 4; p++) {
                int row = (tid >> 3) + p * 32, f4 = tid & 7;
                *(uint2*)&smA[buf][row * LDA + f4 * 4] = make_uint2(la[2 * p], la[2 * p + 1]);
            }
        } else {
#pragma unroll
            for (int p = 0; p < 2; p++) {
                int row = (tid >> 2) + p * 64, u4 = tid & 3;
                *(uint4*)&smA[buf][row * LDA + u4 * 8] =
                    make_uint4(la[4 * p], la[4 * p + 1], la[4 * p + 2], la[4 * p + 3]);
            }
        }
    };
    auto loadB = [&](int kc) {
        if constexpr (sizeof(TB) == 4) {
#pragma unroll
            for (int j = 0; j < 4; j++) {
                int row = tid >> 3, c4 = (tid & 7) + j * 8;
                float4 v = *(const float4*)(Bg + (size_t)(kc + row) * N + bn + c4 * 4);
                lb[2 * j] = cvt2(v.x, v.y);
                lb[2 * j + 1] = cvt2(v.z, v.w);
            }
        } else {
#pragma unroll
            for (int j = 0; j < 2; j++) {
                int row = tid >> 3, u4 = (tid & 7) + j * 8;
                uint4 v = *(const uint4*)(Bg + (size_t)(kc + row) * N + bn + u4 * 8);
                lb[4 * j] = v.x; lb[4 * j + 1] = v.y;
                lb[4 * j + 2] = v.z; lb[4 * j + 3] = v.w;
            }
        }
    };
    auto storeB = [&](int buf) {
        if constexpr (sizeof(TB) == 4) {
#pragma unroll
            for (int j = 0; j < 4; j++) {
                int row = tid >> 3, c4 = (tid & 7) + j * 8;
                *(uint2*)&smB[buf][row * LDB + c4 * 4] = make_uint2(lb[2 * j], lb[2 * j + 1]);
            }
        } else {
#pragma unroll
            for (int j = 0; j < 2; j++) {
                int row = tid >> 3, u4 = (tid & 7) + j * 8;
                *(uint4*)&smB[buf][row * LDB + u4 * 8] =
                    make_uint4(lb[4 * j], lb[4 * j + 1], lb[4 * j + 2], lb[4 * j + 3]);
            }
        }
    };
    auto compute = [&](int buf) {
#pragma unroll
        for (int ks = 0; ks < 2; ks++) {
            const int k0 = ks * 16;
            uint32_t af[2][4], bf[4][4];
#pragma unroll
            for (int mt = 0; mt < 2; mt++) {
                uint32_t addr = (uint32_t)__cvta_generic_to_shared(
                    &smA[buf][(wm * 32 + mt * 16 + (lane & 15)) * LDA + k0 + (lane >> 4) * 8]);
                ldsm4(af[mt], addr);
            }
#pragma unroll
            for (int pr = 0; pr < 4; pr++) {
                uint32_t addr = (uint32_t)__cvta_generic_to_shared(
                    &smB[buf][(k0 + (lane & 15)) * LDB + wn * 64 + pr * 16 + (lane >> 4) * 8]);
                ldsm4t(bf[pr], addr);
            }
#pragma unroll
            for (int mt = 0; mt < 2; mt++)
#pragma unroll
                for (int nt = 0; nt < 8; nt++)
                    mma16816(acc[mt][nt], af[mt],
                             bf[nt >> 1][(nt & 1) * 2], bf[nt >> 1][(nt & 1) * 2 + 1]);
        }
    };

    // ---- mainloop: double-buffered
    const int nch = K / 32;
    loadA(0); loadB(0);
    storeA(0); storeB(0);
    __syncthreads();
    for (int ch = 0; ch < nch; ch++) {
        const int p = ch & 1;
        if (ch + 1 < nch) { loadA((ch + 1) * 32); loadB((ch + 1) * 32); }
        compute(p);
        if (ch + 1 < nch) {
            storeA(1 - p); storeB(1 - p);
            __syncthreads();
        }
    }

    // ---- epilogue
#pragma unroll
    for (int mt = 0; mt < 2; mt++) {
        const int r0 = bm + wm * 32 + mt * 16 + (lane >> 2);
        const int r1 = r0 + 8;
        float sc0 = 1.f, sh0 = 0.f, sc1 = 1.f, sh1 = 0.f;
        if (EPI == 0 || EPI == 1) {
            sh0 = bias ? bias[r0] : 0.f;
            sh1 = bias ? bias[r1] : 0.f;
        } else if (EPI == 3 || EPI == 4) {
            sc0 = scale[r0]; sh0 = shift[r0];
            sc1 = scale[r1]; sh1 = shift[r1];
        }
#pragma unroll
        for (int nt = 0; nt < 8; nt++) {
            const int c = bn + wn * 64 + nt * 8 + (lane & 3) * 2;
            float v00 = acc[mt][nt][0] * sc0 + sh0;
            float v01 = acc[mt][nt][1] * sc0 + sh0;
            float v10 = acc[mt][nt][2] * sc1 + sh1;
            float v11 = acc[mt][nt][3] * sc1 + sh1;
            if (EPI == 0 || EPI == 3) {
                uint16_t* Cb = (uint16_t*)Cv + (size_t)bz * strC;
                *(uint32_t*)&Cb[(size_t)r0 * N + c] = cvt2(v00, v01);
                *(uint32_t*)&Cb[(size_t)r1 * N + c] = cvt2(v10, v11);
            } else if (EPI == 1) {
                uint16_t* Cb = (uint16_t*)Cv + (size_t)bz * strC;
                Cb[(size_t)c * M + r0]       = f2b(v00);
                Cb[(size_t)(c + 1) * M + r0] = f2b(v01);
                Cb[(size_t)c * M + r1]       = f2b(v10);
                Cb[(size_t)(c + 1) * M + r1] = f2b(v11);
            } else if (EPI == 2) {
                float* Cb = (float*)Cv + (size_t)bz * strC;
                *(float2*)&Cb[(size_t)r0 * N + c] = make_float2(v00, v01);
                *(float2*)&Cb[(size_t)r1 * N + c] = make_float2(v10, v11);
            } else { // EPI == 4
                float* Cb = (float*)Cv + (size_t)bz * strC;
                const float* Rb = resid + (size_t)bz * sR;
                float2 q0 = *(const float2*)&Rb[(size_t)r0 * N + c];
                float2 q1 = *(const float2*)&Rb[(size_t)r1 * N + c];
                *(float2*)&Cb[(size_t)r0 * N + c] =
                    make_float2(fmaxf(v00 + q0.x, 0.f), fmaxf(v01 + q0.y, 0.f));
                *(float2*)&Cb[(size_t)r1 * N + c] =
                    make_float2(fmaxf(v10 + q1.x, 0.f), fmaxf(v11 + q1.y, 0.f));
            }
        }
    }
}

// ---------------------------------------------------------------------------
// Row softmax: fp32 logits in, bf16 out. One block per row of 4096.
// ---------------------------------------------------------------------------
__global__ __launch_bounds__(256)
void softmax_rows(const float* __restrict__ S, uint16_t* __restrict__ Attn)
{
    __shared__ float red[256];
    size_t row = blockIdx.x;
    const float* r = S + row * NPIX;
    int t = threadIdx.x;

    float4 v[4];
#pragma unroll
    for (int i = 0; i < 4; i++) v[i] = ((const float4*)r)[t + i * 256];

    float mx = v[0].x;
#pragma unroll
    for (int i = 0; i < 4; i++)
        mx = fmaxf(mx, fmaxf(fmaxf(v[i].x, v[i].y), fmaxf(v[i].z, v[i].w)));
    red[t] = mx;
    __syncthreads();
#pragma unroll
    for (int s = 128; s > 0; s >>= 1) {
        if (t < s) red[t] = fmaxf(red[t], red[t + s]);
        __syncthreads();
    }
    mx = red[0];
    __syncthreads();

    float sum = 0.0f;
#pragma unroll
    for (int i = 0; i < 4; i++) {
        v[i].x = __expf(v[i].x - mx); sum += v[i].x;
        v[i].y = __expf(v[i].y - mx); sum += v[i].y;
        v[i].z = __expf(v[i].z - mx); sum += v[i].z;
        v[i].w = __expf(v[i].w - mx); sum += v[i].w;
    }
    red[t] = sum;
    __syncthreads();
#pragma unroll
    for (int s = 128; s > 0; s >>= 1) {
        if (t < s) red[t] += red[t + s];
        __syncthreads();
    }
    float inv = 1.0f / red[0];

    uint32_t* o = (uint32_t*)(Attn + row * NPIX);
#pragma unroll
    for (int i = 0; i < 4; i++) {
        int idx = t + i * 256;
        o[2 * idx]     = cvt2(v[i].x * inv, v[i].y * inv);
        o[2 * idx + 1] = cvt2(v[i].z * inv, v[i].w * inv);
    }
}

// ---------------------------------------------------------------------------
// Launch
// ---------------------------------------------------------------------------
extern "C" void kernel_launch(void* const* d_in, const int* in_sizes, int n_in,
                              void* d_out, int out_size)
{
    const float* xA   = (const float*)d_in[0];
    const float* wk   = (const float*)d_in[1];
    const float* bk   = (const float*)d_in[2];
    const float* wv   = (const float*)d_in[3];
    const float* bv   = (const float*)d_in[4];
    const float* wq   = (const float*)d_in[5];
    const float* bq   = (const float*)d_in[6];
    const float* wwg  = (const float*)d_in[7];
    const float* bn1g = (const float*)d_in[8];
    const float* bn1b = (const float*)d_in[9];
    const float* bn1m = (const float*)d_in[10];
    const float* bn1v = (const float*)d_in[11];
    const float* wout = (const float*)d_in[12];
    const float* bout = (const float*)d_in[13];
    const float* bn2g = (const float*)d_in[14];
    const float* bn2b = (const float*)d_in[15];
    const float* bn2m = (const float*)d_in[16];
    const float* bn2v = (const float*)d_in[17];
    float* out = (float*)d_out;

    uint16_t *pkb, *pvT, *pqb, *pattn, *pavb, *pavwb;
    float *pS, *psc1, *psh1, *psc2, *psh2;
    cudaGetSymbolAddress((void**)&pkb,   g_kb);
    cudaGetSymbolAddress((void**)&pvT,   g_vT);
    cudaGetSymbolAddress((void**)&pqb,   g_qb);
    cudaGetSymbolAddress((void**)&pS,    g_S);
    cudaGetSymbolAddress((void**)&pattn, g_attn);
    cudaGetSymbolAddress((void**)&pavb,  g_avb);
    cudaGetSymbolAddress((void**)&pavwb, g_avwb);
    cudaGetSymbolAddress((void**)&psc1,  g_sc1);
    cudaGetSymbolAddress((void**)&psh1,  g_sh1);
    cudaGetSymbolAddress((void**)&psc2,  g_sc2);
    cudaGetSymbolAddress((void**)&psh2,  g_sh2);

    fold_kernel<<<1, 512>>>(bn1g, bn1b, bn1m, bn1v, bn2g, bn2b, bn2m, bn2v, bout);

    const size_t sX  = (size_t)CCH * NPIX;
    const size_t sIC = (size_t)ICH * NPIX;
    const size_t sS  = (size_t)NPIX * NPIX;

    // 1) projections: D[o,n] = W[o,c] * xA[c,n] + bias
    {
        dim3 grd(NPIX / 128, ICH / 128, BATCH);
        hmma_gemm<float, float, 0><<<grd, 256>>>(wk, xA, pkb, ICH, NPIX, CCH,
                                                 0, sX, sIC, bk, nullptr, nullptr, nullptr, 0);
        hmma_gemm<float, float, 0><<<grd, 256>>>(wq, xA, pqb, ICH, NPIX, CCH,
                                                 0, sX, sIC, bq, nullptr, nullptr, nullptr, 0);
        hmma_gemm<float, float, 1><<<grd, 256>>>(wv, xA, pvT, ICH, NPIX, CCH,
                                                 0, sX, sIC, bv, nullptr, nullptr, nullptr, 0);
    }
    // 2) S[n,m] = sum_c vT[n,c] * q[c,m]   (fp32 out)
    {
        dim3 grd(NPIX / 128, NPIX / 128, BATCH);
        hmma_gemm<uint16_t, uint16_t, 2><<<grd, 256>>>(pvT, pqb, pS, NPIX, NPIX, ICH,
                                                       sIC, sIC, sS,
                                                       nullptr, nullptr, nullptr, nullptr, 0);
    }
    // 3) softmax rows -> bf16 attn
    softmax_rows<<<BATCH * NPIX, 256>>>(pS, pattn);

    // 4) av[c,m] = sum_n k[c,n] * attn[n,m]
    {
        dim3 grd(NPIX / 128, ICH / 128, BATCH);
        hmma_gemm<uint16_t, uint16_t, 0><<<grd, 256>>>(pkb, pattn, pavb, ICH, NPIX, NPIX,
                                                       sIC, sS, sIC,
                                                       nullptr, nullptr, nullptr, nullptr, 0);
    }
    // 5) avw = bn1(wwg @ av)
    {
        dim3 grd(NPIX / 128, ICH / 128, BATCH);
        hmma_gemm<float, uint16_t, 3><<<grd, 256>>>(wwg, pavb, pavwb, ICH, NPIX, ICH,
                                                    0, sIC, sIC,
                                                    nullptr, psc1, psh1, nullptr, 0);
    }
    // 6) out = relu(bn2(wout @ avw) + xA)
    {
        dim3 grd(NPIX / 128, CCH / 128, BATCH);
        hmma_gemm<float, uint16_t, 4><<<grd, 256>>>(wout, pavwb, out, CCH, NPIX, ICH,
                                                    0, sIC, sX,
                                                    nullptr, psc2, psh2, xA, sX);
    }
}

// round 4
// speedup vs baseline: 5.7563x; 1.0264x over previous
#include <cuda_runtime.h>
#include <cuda_bf16.h>
#include <cstdint>

#define BATCH 4
#define CCH   512
#define ICH   256
#define NPIX  4096
#define BNEPS 1e-5f

// ---------------------------------------------------------------------------
// Scratch (device globals)
// ---------------------------------------------------------------------------
static __device__ uint16_t g_xb  [(size_t)BATCH * CCH * NPIX];   // xA bf16
static __device__ uint16_t g_wkqv[768 * CCH];                    // [wk;wq;wv] bf16
static __device__ float    g_bkqv[768];
static __device__ uint16_t g_kqv [(size_t)BATCH * 768 * NPIX];   // k|q|v bf16
static __device__ uint16_t g_w2b [ICH * ICH];                    // wwg bf16
static __device__ uint16_t g_w3b [CCH * ICH];                    // wout bf16
static __device__ float    g_S   [(size_t)BATCH * NPIX * NPIX];  // logits fp32
static __device__ uint16_t g_attn[(size_t)BATCH * NPIX * NPIX];  // softmax bf16
static __device__ uint16_t g_avb [(size_t)BATCH * ICH * NPIX];
static __device__ uint16_t g_avwb[(size_t)BATCH * ICH * NPIX];
static __device__ float g_sc1[ICH], g_sh1[ICH], g_sc2[CCH], g_sh2[CCH];

// ---------------------------------------------------------------------------
// Helpers
// ---------------------------------------------------------------------------
__device__ __forceinline__ uint32_t cvt2(float a, float b) {
    __nv_bfloat162 h = __floats2bfloat162_rn(a, b);
    return *(uint32_t*)&h;
}
__device__ __forceinline__ uint16_t f2b(float x) {
    __nv_bfloat16 b = __float2bfloat16_rn(x);
    return *(uint16_t*)&b;
}
__device__ __forceinline__ void ldsm4(uint32_t* r, uint32_t addr) {
    asm volatile("ldmatrix.sync.aligned.m8n8.x4.shared.b16 {%0,%1,%2,%3}, [%4];"
                 : "=r"(r[0]), "=r"(r[1]), "=r"(r[2]), "=r"(r[3]) : "r"(addr));
}
__device__ __forceinline__ void ldsm4t(uint32_t* r, uint32_t addr) {
    asm volatile("ldmatrix.sync.aligned.m8n8.x4.trans.shared.b16 {%0,%1,%2,%3}, [%4];"
                 : "=r"(r[0]), "=r"(r[1]), "=r"(r[2]), "=r"(r[3]) : "r"(addr));
}
__device__ __forceinline__ void mma16816(float* c, const uint32_t* a,
                                         uint32_t b0, uint32_t b1) {
    asm volatile(
        "mma.sync.aligned.m16n8k16.row.col.f32.bf16.bf16.f32 "
        "{%0,%1,%2,%3}, {%4,%5,%6,%7}, {%8,%9}, {%0,%1,%2,%3};"
        : "+f"(c[0]), "+f"(c[1]), "+f"(c[2]), "+f"(c[3])
        : "r"(a[0]), "r"(a[1]), "r"(a[2]), "r"(a[3]), "r"(b0), "r"(b1));
}
__device__ __forceinline__ void cpa16(uint32_t dst, const void* src) {
    asm volatile("cp.async.cg.shared.global [%0], [%1], 16;" :: "r"(dst), "l"(src));
}

// ---------------------------------------------------------------------------
// Prep: fold BN, convert & concat weights to bf16
// ---------------------------------------------------------------------------
__global__ void prep_weights(const float* __restrict__ wk, const float* __restrict__ bk,
                             const float* __restrict__ wv, const float* __restrict__ bv,
                             const float* __restrict__ wq, const float* __restrict__ bq,
                             const float* __restrict__ wwg,
                             const float* __restrict__ g1, const float* __restrict__ b1,
                             const float* __restrict__ m1, const float* __restrict__ v1,
                             const float* __restrict__ wout, const float* __restrict__ bout,
                             const float* __restrict__ g2, const float* __restrict__ b2,
                             const float* __restrict__ m2, const float* __restrict__ v2)
{
    int i = blockIdx.x * blockDim.x + threadIdx.x;
    int tot = blockDim.x * gridDim.x;
    for (int idx = i; idx < 768 * CCH; idx += tot) {
        int r = idx / CCH, c = idx % CCH;
        float v = (r < 256) ? wk[r * CCH + c]
                : (r < 512) ? wq[(r - 256) * CCH + c]
                            : wv[(r - 512) * CCH + c];
        g_wkqv[idx] = f2b(v);
    }
    for (int idx = i; idx < ICH * ICH; idx += tot) g_w2b[idx] = f2b(wwg[idx]);
    for (int idx = i; idx < CCH * ICH; idx += tot) g_w3b[idx] = f2b(wout[idx]);
    if (i < 768) g_bkqv[i] = (i < 256) ? bk[i] : (i < 512) ? bq[i - 256] : bv[i - 512];
    if (i < ICH) {
        float s = g1[i] * rsqrtf(v1[i] + BNEPS);
        g_sc1[i] = s; g_sh1[i] = b1[i] - m1[i] * s;
    }
    if (i < CCH) {
        float s = g2[i] * rsqrtf(v2[i] + BNEPS);
        g_sc2[i] = s; g_sh2[i] = (bout[i] - m2[i]) * s + b2[i];
    }
}

__global__ void cvt_x(const float* __restrict__ x, uint16_t* __restrict__ o)
{
    size_t i = (size_t)blockIdx.x * blockDim.x + threadIdx.x;   // per float4
    const size_t n4 = (size_t)BATCH * CCH * NPIX / 4;
    if (i < n4) {
        float4 v = ((const float4*)x)[i];
        ((uint2*)o)[i] = make_uint2(cvt2(v.x, v.y), cvt2(v.z, v.w));
    }
}

// ---------------------------------------------------------------------------
// bf16 HMMA GEMM, 4-stage cp.async pipeline.
//   D[m,n] = sum_k A * B[k,n], B row-major [K,N].
//   TRA=false: A row-major [M,K]. TRA=true: A stored [K,M] (A[m,k]=Ag[k,m]).
//   Tile 128x128x32, 256 thr = 8 warps (4m x 2n), warp = 32m x 64n.
// EPI: 0 +bias[m]                      -> bf16 [M,N]
//      2 none                          -> fp32 [M,N]
//      3 *scale[m]+shift[m]            -> bf16 [M,N]
//      4 *scale[m]+shift[m]+resid,relu -> fp32 [M,N]
// ---------------------------------------------------------------------------
template<bool TRA, int EPI>
__global__ __launch_bounds__(256, 2)
void hmma_gemm(const uint16_t* __restrict__ A, const uint16_t* __restrict__ B,
               void* __restrict__ Cv, int M, int N, int K,
               size_t strA, size_t strB, size_t strC,
               const float* __restrict__ bias,
               const float* __restrict__ scale, const float* __restrict__ shift,
               const float* __restrict__ resid, size_t sR)
{
    constexpr int ST  = 4;
    constexpr int ASZ = TRA ? 32 * 136 : 128 * 56;   // elems per A stage
    constexpr int BSZ = 32 * 136;
    extern __shared__ __align__(16) uint16_t sh[];
    uint16_t* smA = sh;
    uint16_t* smB = sh + ST * ASZ;

    const int tid = threadIdx.x, lane = tid & 31, wid = tid >> 5;
    const int wm = wid & 3, wn = wid >> 2;
    const int bz = blockIdx.z, bm = blockIdx.y * 128, bn = blockIdx.x * 128;
    const uint16_t* Ag = A + (size_t)bz * strA;
    const uint16_t* Bg = B + (size_t)bz * strB;

    float acc[2][8][4] = {};

    auto loadA = [&](int kc, int s) {
        if constexpr (TRA) {
            int row = tid >> 3, c16 = tid & 7;
#pragma unroll
            for (int j = 0; j < 2; j++) {
                int ch = c16 + j * 8;
                cpa16((uint32_t)__cvta_generic_to_shared(smA + s * ASZ + row * 136 + ch * 8),
                      Ag + (size_t)(kc + row) * M + bm + ch * 8);
            }
        } else {
            int row = tid >> 1, half = tid & 1;
#pragma unroll
            for (int j = 0; j < 2; j++) {
                int ch = half * 2 + j;
                cpa16((uint32_t)__cvta_generic_to_shared(smA + s * ASZ + row * 56 + ch * 8),
                      Ag + (size_t)(bm + row) * K + kc + ch * 8);
            }
        }
    };
    auto loadB = [&](int kc, int s) {
        int row = tid >> 3, c16 = tid & 7;
#pragma unroll
        for (int j = 0; j < 2; j++) {
            int ch = c16 + j * 8;
            cpa16((uint32_t)__cvta_generic_to_shared(smB + s * BSZ + row * 136 + ch * 8),
                  Bg + (size_t)(kc + row) * N + bn + ch * 8);
        }
    };
    auto compute = [&](int s) {
        uint16_t* pA = smA + s * ASZ;
        uint16_t* pB = smB + s * BSZ;
#pragma unroll
        for (int ks = 0; ks < 2; ks++) {
            const int k0 = ks * 16;
            uint32_t af[2][4], bf[4][4];
#pragma unroll
            for (int mt = 0; mt < 2; mt++) {
                if constexpr (TRA) {
                    uint32_t r[4];
                    ldsm4t(r, (uint32_t)__cvta_generic_to_shared(
                        pA + (k0 + (lane & 15)) * 136 + wm * 32 + mt * 16 + (lane >> 4) * 8));
                    af[mt][0] = r[0]; af[mt][1] = r[2];
                    af[mt][2] = r[1]; af[mt][3] = r[3];
                } else {
                    ldsm4(af[mt], (uint32_t)__cvta_generic_to_shared(
                        pA + (wm * 32 + mt * 16 + (lane & 15)) * 56 + k0 + (lane >> 4) * 8));
                }
            }
#pragma unroll
            for (int pr = 0; pr < 4; pr++) {
                ldsm4t(bf[pr], (uint32_t)__cvta_generic_to_shared(
                    pB + (k0 + (lane & 15)) * 136 + wn * 64 + pr * 16 + (lane >> 4) * 8));
            }
#pragma unroll
            for (int mt = 0; mt < 2; mt++)
#pragma unroll
                for (int nt = 0; nt < 8; nt++)
                    mma16816(acc[mt][nt], af[mt],
                             bf[nt >> 1][(nt & 1) * 2], bf[nt >> 1][(nt & 1) * 2 + 1]);
        }
    };

    const int nch = K / 32;
#pragma unroll
    for (int s = 0; s < ST - 1; s++) {
        if (s < nch) { loadA(s * 32, s); loadB(s * 32, s); }
        asm volatile("cp.async.commit_group;" ::: "memory");
    }
    for (int ch = 0; ch < nch; ch++) {
        asm volatile("cp.async.wait_group %0;" :: "n"(ST - 2) : "memory");
        __syncthreads();
        compute(ch & (ST - 1));
        int nx = ch + ST - 1;
        if (nx < nch) { loadA(nx * 32, nx & (ST - 1)); loadB(nx * 32, nx & (ST - 1)); }
        asm volatile("cp.async.commit_group;" ::: "memory");
    }

    // ---- epilogue
#pragma unroll
    for (int mt = 0; mt < 2; mt++) {
        const int r0 = bm + wm * 32 + mt * 16 + (lane >> 2);
        const int r1 = r0 + 8;
        float sc0 = 1.f, sh0 = 0.f, sc1 = 1.f, sh1 = 0.f;
        if (EPI == 0) {
            sh0 = bias ? bias[r0] : 0.f;
            sh1 = bias ? bias[r1] : 0.f;
        } else if (EPI == 3 || EPI == 4) {
            sc0 = scale[r0]; sh0 = shift[r0];
            sc1 = scale[r1]; sh1 = shift[r1];
        }
#pragma unroll
        for (int nt = 0; nt < 8; nt++) {
            const int c = bn + wn * 64 + nt * 8 + (lane & 3) * 2;
            float v00 = acc[mt][nt][0] * sc0 + sh0;
            float v01 = acc[mt][nt][1] * sc0 + sh0;
            float v10 = acc[mt][nt][2] * sc1 + sh1;
            float v11 = acc[mt][nt][3] * sc1 + sh1;
            if (EPI == 0 || EPI == 3) {
                uint16_t* Cb = (uint16_t*)Cv + (size_t)bz * strC;
                *(uint32_t*)&Cb[(size_t)r0 * N + c] = cvt2(v00, v01);
                *(uint32_t*)&Cb[(size_t)r1 * N + c] = cvt2(v10, v11);
            } else if (EPI == 2) {
                float* Cb = (float*)Cv + (size_t)bz * strC;
                *(float2*)&Cb[(size_t)r0 * N + c] = make_float2(v00, v01);
                *(float2*)&Cb[(size_t)r1 * N + c] = make_float2(v10, v11);
            } else { // EPI == 4
                float* Cb = (float*)Cv + (size_t)bz * strC;
                const float* Rb = resid + (size_t)bz * sR;
                float2 q0 = *(const float2*)&Rb[(size_t)r0 * N + c];
                float2 q1 = *(const float2*)&Rb[(size_t)r1 * N + c];
                *(float2*)&Cb[(size_t)r0 * N + c] =
                    make_float2(fmaxf(v00 + q0.x, 0.f), fmaxf(v01 + q0.y, 0.f));
                *(float2*)&Cb[(size_t)r1 * N + c] =
                    make_float2(fmaxf(v10 + q1.x, 0.f), fmaxf(v11 + q1.y, 0.f));
            }
        }
    }
}

// ---------------------------------------------------------------------------
// Row softmax: fp32 logits in, bf16 out. One block per row of 4096.
// ---------------------------------------------------------------------------
__global__ __launch_bounds__(256)
void softmax_rows(const float* __restrict__ S, uint16_t* __restrict__ Attn)
{
    __shared__ float red[256];
    size_t row = blockIdx.x;
    const float* r = S + row * NPIX;
    int t = threadIdx.x;

    float4 v[4];
#pragma unroll
    for (int i = 0; i < 4; i++) v[i] = ((const float4*)r)[t + i * 256];

    float mx = v[0].x;
#pragma unroll
    for (int i = 0; i < 4; i++)
        mx = fmaxf(mx, fmaxf(fmaxf(v[i].x, v[i].y), fmaxf(v[i].z, v[i].w)));
    red[t] = mx;
    __syncthreads();
#pragma unroll
    for (int s = 128; s > 0; s >>= 1) {
        if (t < s) red[t] = fmaxf(red[t], red[t + s]);
        __syncthreads();
    }
    mx = red[0];
    __syncthreads();

    float sum = 0.0f;
#pragma unroll
    for (int i = 0; i < 4; i++) {
        v[i].x = __expf(v[i].x - mx); sum += v[i].x;
        v[i].y = __expf(v[i].y - mx); sum += v[i].y;
        v[i].z = __expf(v[i].z - mx); sum += v[i].z;
        v[i].w = __expf(v[i].w - mx); sum += v[i].w;
    }
    red[t] = sum;
    __syncthreads();
#pragma unroll
    for (int s = 128; s > 0; s >>= 1) {
        if (t < s) red[t] += red[t + s];
        __syncthreads();
    }
    float inv = 1.0f / red[0];

    uint32_t* o = (uint32_t*)(Attn + row * NPIX);
#pragma unroll
    for (int i = 0; i < 4; i++) {
        int idx = t + i * 256;
        o[2 * idx]     = cvt2(v[i].x * inv, v[i].y * inv);
        o[2 * idx + 1] = cvt2(v[i].z * inv, v[i].w * inv);
    }
}

// ---------------------------------------------------------------------------
// Launch
// ---------------------------------------------------------------------------
extern "C" void kernel_launch(void* const* d_in, const int* in_sizes, int n_in,
                              void* d_out, int out_size)
{
    const float* xA   = (const float*)d_in[0];
    const float* wk   = (const float*)d_in[1];
    const float* bk   = (const float*)d_in[2];
    const float* wv   = (const float*)d_in[3];
    const float* bv   = (const float*)d_in[4];
    const float* wq   = (const float*)d_in[5];
    const float* bq   = (const float*)d_in[6];
    const float* wwg  = (const float*)d_in[7];
    const float* bn1g = (const float*)d_in[8];
    const float* bn1b = (const float*)d_in[9];
    const float* bn1m = (const float*)d_in[10];
    const float* bn1v = (const float*)d_in[11];
    const float* wout = (const float*)d_in[12];
    const float* bout = (const float*)d_in[13];
    const float* bn2g = (const float*)d_in[14];
    const float* bn2b = (const float*)d_in[15];
    const float* bn2m = (const float*)d_in[16];
    const float* bn2v = (const float*)d_in[17];
    float* out = (float*)d_out;

    const int SMEM_NT = 4 * (128 * 56 + 32 * 136) * 2;  // 92160 B
    const int SMEM_T  = 4 * (32 * 136 + 32 * 136) * 2;  // 69632 B
    cudaFuncSetAttribute(hmma_gemm<false, 0>, cudaFuncAttributeMaxDynamicSharedMemorySize, SMEM_NT);
    cudaFuncSetAttribute(hmma_gemm<false, 3>, cudaFuncAttributeMaxDynamicSharedMemorySize, SMEM_NT);
    cudaFuncSetAttribute(hmma_gemm<false, 4>, cudaFuncAttributeMaxDynamicSharedMemorySize, SMEM_NT);
    cudaFuncSetAttribute(hmma_gemm<true, 2>,  cudaFuncAttributeMaxDynamicSharedMemorySize, SMEM_T);

    uint16_t *pxb, *pwkqv, *pkqv, *pw2, *pw3, *pattn, *pavb, *pavwb;
    float *pS, *pbkqv, *psc1, *psh1, *psc2, *psh2;
    cudaGetSymbolAddress((void**)&pxb,   g_xb);
    cudaGetSymbolAddress((void**)&pwkqv, g_wkqv);
    cudaGetSymbolAddress((void**)&pbkqv, g_bkqv);
    cudaGetSymbolAddress((void**)&pkqv,  g_kqv);
    cudaGetSymbolAddress((void**)&pw2,   g_w2b);
    cudaGetSymbolAddress((void**)&pw3,   g_w3b);
    cudaGetSymbolAddress((void**)&pS,    g_S);
    cudaGetSymbolAddress((void**)&pattn, g_attn);
    cudaGetSymbolAddress((void**)&pavb,  g_avb);
    cudaGetSymbolAddress((void**)&pavwb, g_avwb);
    cudaGetSymbolAddress((void**)&psc1,  g_sc1);
    cudaGetSymbolAddress((void**)&psh1,  g_sh1);
    cudaGetSymbolAddress((void**)&psc2,  g_sc2);
    cudaGetSymbolAddress((void**)&psh2,  g_sh2);

    // 0) prep
    prep_weights<<<256, 256>>>(wk, bk, wv, bv, wq, bq, wwg,
                               bn1g, bn1b, bn1m, bn1v,
                               wout, bout, bn2g, bn2b, bn2m, bn2v);
    cvt_x<<<(BATCH * CCH * NPIX / 4 + 255) / 256, 256>>>(xA, pxb);

    const size_t sX   = (size_t)CCH * NPIX;
    const size_t sIC  = (size_t)ICH * NPIX;
    const size_t sKQV = (size_t)768 * NPIX;
    const size_t sS   = (size_t)NPIX * NPIX;

    // 1) fused projections: kqv[o,n] = Wkqv[o,c] * xb[c,n] + b, o in [0,768)
    {
        dim3 grd(NPIX / 128, 768 / 128, BATCH);
        hmma_gemm<false, 0><<<grd, 256, SMEM_NT>>>(pwkqv, pxb, pkqv, 768, NPIX, CCH,
                                                   0, sX, sKQV, pbkqv,
                                                   nullptr, nullptr, nullptr, 0);
    }
    // 2) S[n,m] = sum_c v[c,n] * q[c,m]   (A = v via TRANSA, fp32 out)
    {
        dim3 grd(NPIX / 128, NPIX / 128, BATCH);
        hmma_gemm<true, 2><<<grd, 256, SMEM_T>>>(pkqv + (size_t)512 * NPIX,
                                                 pkqv + (size_t)256 * NPIX,
                                                 pS, NPIX, NPIX, ICH,
                                                 sKQV, sKQV, sS,
                                                 nullptr, nullptr, nullptr, nullptr, 0);
    }
    // 3) softmax rows -> bf16 attn
    softmax_rows<<<BATCH * NPIX, 256>>>(pS, pattn);

    // 4) av[c,m] = sum_n k[c,n] * attn[n,m]
    {
        dim3 grd(NPIX / 128, ICH / 128, BATCH);
        hmma_gemm<false, 0><<<grd, 256, SMEM_NT>>>(pkqv, pattn, pavb, ICH, NPIX, NPIX,
                                                   sKQV, sS, sIC,
                                                   nullptr, nullptr, nullptr, nullptr, 0);
    }
    // 5) avw = bn1(wwg @ av)
    {
        dim3 grd(NPIX / 128, ICH / 128, BATCH);
        hmma_gemm<false, 3><<<grd, 256, SMEM_NT>>>(pw2, pavb, pavwb, ICH, NPIX, ICH,
                                                   0, sIC, sIC,
                                                   nullptr, psc1, psh1, nullptr, 0);
    }
    // 6) out = relu(bn2(wout @ avw) + xA)
    {
        dim3 grd(NPIX / 128, CCH / 128, BATCH);
        hmma_gemm<false, 4><<<grd, 256, SMEM_NT>>>(pw3, pavwb, out, CCH, NPIX, ICH,
                                                   0, sIC, sX,
                                                   nullptr, psc2, psh2, xA, sX);
    }
}